// round 12
// baseline (speedup 1.0000x reference)
#include <cuda_runtime.h>
#include <cuda_fp16.h>
#include <cstdint>

#define NMAX 50000
#define EMAX 1600000
#define D 128
#define CAP 128    // per-node bucket capacity; P(Poisson(32) > 128) ~ 1e-40
#define APAD 68    // A smem row pad (words): 64 nodes + 4 -> 272B rows (16B aligned)

typedef unsigned long long ull;

// Scratch (device globals: no runtime allocation allowed)
__device__ float g_cntf[NMAX];                    // in-degree (float, exact)
__device__ int   g_bucket[(size_t)NMAX * CAP];    // src lists, node-strided
__device__ uint2 g_xsh[(size_t)NMAX * 32];        // x*dinv as half2 pairs (8B/lane)
__device__ float g_agg[(size_t)NMAX * D];
__device__ ull   g_Wtd[(size_t)D * D];            // W transposed, dup'd f32x2

#define FMA_F32X2(d, a, b, c) \
    asm("fma.rn.f32x2 %0, %1, %2, %3;" : "=l"(d) : "l"(a), "l"(b), "l"(c))
#define UNPACK2(lo, hi, in) \
    asm("mov.b64 {%0, %1}, %2;" : "=r"(lo), "=r"(hi) : "l"(in))

__device__ __forceinline__ unsigned h2_bits(__half2 h) {
    return *reinterpret_cast<unsigned*>(&h);
}
__device__ __forceinline__ float2 bits_f2(unsigned u) {
    __half2 h = *reinterpret_cast<__half2*>(&u);
    return __half22float2(h);
}

// ---------------------------------------------------------------------------
// fill: bucket edges by dst, 4 edges per thread (overlapped atomic chains).
// Per-block inline dtype detection (int64 values < 2^31 -> odd words zero).
// ---------------------------------------------------------------------------
__global__ void fill_kernel(const void* __restrict__ edge, int E, int nwords) {
    int flag = 0;
    const int* e32 = (const int*)edge;
    for (int i = 1 + 2 * threadIdx.x; i < 2048 && i < nwords;
         i += 2 * blockDim.x)
        flag |= e32[i];
    int is64 = !__syncthreads_or(flag);

    int base = (blockIdx.x * blockDim.x + threadIdx.x) * 4;
    int s[4], d[4], pos[4];
#pragma unroll
    for (int j = 0; j < 4; j++) {
        int i = base + j;
        if (i < E) {
            if (is64) {
                const long long* e64 = (const long long*)edge;
                s[j] = (int)e64[i];
                d[j] = (int)e64[E + i];
            } else {
                s[j] = e32[i];
                d[j] = e32[E + i];
            }
        } else {
            s[j] = 0;
            d[j] = -1;
        }
    }
#pragma unroll
    for (int j = 0; j < 4; j++)
        if (d[j] >= 0) pos[j] = (int)atomicAdd(&g_cntf[d[j]], 1.0f);
#pragma unroll
    for (int j = 0; j < 4; j++)
        if (d[j] >= 0 && pos[j] < CAP)
            g_bucket[(size_t)d[j] * CAP + pos[j]] = s[j];
}

// ---------------------------------------------------------------------------
// wtrans: g_Wtd[k][f] = dup(W[f][k]) as packed f32x2 (one-time, 16K elems)
// ---------------------------------------------------------------------------
__global__ void wtrans_kernel(const float* __restrict__ W) {
    int i = blockIdx.x * blockDim.x + threadIdx.x;
    if (i >= D * D) return;
    int f = i >> 7;
    int k = i & 127;
    unsigned u = __float_as_uint(W[i]);
    g_Wtd[(size_t)k * D + f] = ((ull)u << 32) | u;
}

// ---------------------------------------------------------------------------
// prescale: xsh[i] = half(x[i] * dinv(i))   (dinv = rsqrt(deg+1))
// ---------------------------------------------------------------------------
__global__ void prescale_kernel(const float4* __restrict__ x4, int n) {
    int i = blockIdx.x * blockDim.x + threadIdx.x;
    if (i >= n * 32) return;
    int node = i >> 5;
    float dd = rsqrtf(g_cntf[node] + 1.0f);
    float4 v = __ldg(&x4[i]);
    uint2 u;
    u.x = h2_bits(__floats2half2_rn(v.x * dd, v.y * dd));
    u.y = h2_bits(__floats2half2_rn(v.z * dd, v.w * dd));
    g_xsh[i] = u;
}

// ---------------------------------------------------------------------------
// gather-aggregate. One warp per dst node, lane = 4-feature chunk (uint2 =
// 2x half2 per row). Unroll-8: 8 outstanding LDG.64 per thread. Accumulate
// in fp32. Self-loop folded; row scaled by dinv[dst] at the end.
// ---------------------------------------------------------------------------
__global__ __launch_bounds__(256) void gather_kernel(int n) {
    int node = blockIdx.x * 8 + (threadIdx.x >> 5);
    int lane = threadIdx.x & 31;
    if (node >= n) return;
    const int* row = &g_bucket[(size_t)node * CAP];
    int deg = (int)g_cntf[node];
    if (deg > CAP) deg = CAP;
    float dd = rsqrtf((float)deg + 1.0f);

    float4 a[8];
#pragma unroll
    for (int j = 0; j < 8; j++) a[j] = make_float4(0.f, 0.f, 0.f, 0.f);

    // self-loop contribution
    {
        uint2 u = g_xsh[(size_t)node * 32 + lane];
        float2 lo = bits_f2(u.x);
        float2 hi = bits_f2(u.y);
        a[0] = make_float4(lo.x, lo.y, hi.x, hi.y);
    }

    int e = 0;
    for (; e + 8 <= deg; e += 8) {
        int s[8];
        uint2 u[8];
#pragma unroll
        for (int j = 0; j < 8; j++) s[j] = row[e + j];
#pragma unroll
        for (int j = 0; j < 8; j++) u[j] = __ldg(&g_xsh[(size_t)s[j] * 32 + lane]);
#pragma unroll
        for (int j = 0; j < 8; j++) {
            float2 lo = bits_f2(u[j].x);
            float2 hi = bits_f2(u[j].y);
            a[j].x += lo.x;
            a[j].y += lo.y;
            a[j].z += hi.x;
            a[j].w += hi.y;
        }
    }
    for (; e < deg; e++) {
        int s = row[e];
        uint2 u = __ldg(&g_xsh[(size_t)s * 32 + lane]);
        float2 lo = bits_f2(u.x);
        float2 hi = bits_f2(u.y);
        a[0].x += lo.x; a[0].y += lo.y; a[0].z += hi.x; a[0].w += hi.y;
    }
    float4 acc;
    acc.x = ((a[0].x + a[1].x) + (a[2].x + a[3].x)) + ((a[4].x + a[5].x) + (a[6].x + a[7].x));
    acc.y = ((a[0].y + a[1].y) + (a[2].y + a[3].y)) + ((a[4].y + a[5].y) + (a[6].y + a[7].y));
    acc.z = ((a[0].z + a[1].z) + (a[2].z + a[3].z)) + ((a[4].z + a[5].z) + (a[6].z + a[7].z));
    acc.w = ((a[0].w + a[1].w) + (a[2].w + a[3].w)) + ((a[4].w + a[5].w) + (a[6].w + a[7].w));
    acc.x *= dd; acc.y *= dd; acc.z *= dd; acc.w *= dd;
    reinterpret_cast<float4*>(g_agg)[(size_t)node * 32 + lane] = acc;
}

// ---------------------------------------------------------------------------
// h = agg @ W^T + b ; out = x + relu(h)
// 64 nodes/block, 256 threads. Smem holds ONLY the transposed A tile (35KB)
// -> 3+ blocks/SM. W comes from g_Wtd (pre-transposed + pre-dup'd f32x2,
// L2-resident, same lines for every block). Mainloop per k:
//   2x LDS.128 (A node-pairs, warp-broadcast) + 2x LDG.128 (Wdup) + 16 FFMA2
// -> FFMA2 density 16/21 > 0.5 pipe cap -> fp32-pipe-bound (~68 TF/s).
// ---------------------------------------------------------------------------
__global__ __launch_bounds__(256) void gemm_relu_kernel(
    const float* __restrict__ x, const float* __restrict__ b,
    float* __restrict__ out, int n) {
    __shared__ float Asm[D * APAD];   // [k][node] (transposed tile)

    int tid = threadIdx.x;
    int node0 = blockIdx.x * 64;
    for (int i = tid; i < 64 * D; i += 256) {
        int nl = i >> 7;
        int k = i & 127;
        int node = node0 + nl;
        Asm[k * APAD + nl] = (node < n) ? g_agg[(size_t)node * D + k] : 0.f;
    }
    __syncthreads();

    int lane = tid & 31;
    int wg = tid >> 5;
    int f4 = lane * 4;

    ull acc[4][4];
#pragma unroll
    for (int p = 0; p < 4; p++)
#pragma unroll
        for (int c = 0; c < 4; c++) acc[p][c] = 0ull;

#pragma unroll 4
    for (int k = 0; k < D; k++) {
        const ulonglong2* ap =
            reinterpret_cast<const ulonglong2*>(&Asm[k * APAD + wg * 8]);
        ulonglong2 a01 = ap[0];
        ulonglong2 a23 = ap[1];
        const ulonglong2* wp =
            reinterpret_cast<const ulonglong2*>(&g_Wtd[(size_t)k * D + f4]);
        ulonglong2 w01 = __ldg(&wp[0]);
        ulonglong2 w23 = __ldg(&wp[1]);
        FMA_F32X2(acc[0][0], a01.x, w01.x, acc[0][0]);
        FMA_F32X2(acc[0][1], a01.x, w01.y, acc[0][1]);
        FMA_F32X2(acc[0][2], a01.x, w23.x, acc[0][2]);
        FMA_F32X2(acc[0][3], a01.x, w23.y, acc[0][3]);
        FMA_F32X2(acc[1][0], a01.y, w01.x, acc[1][0]);
        FMA_F32X2(acc[1][1], a01.y, w01.y, acc[1][1]);
        FMA_F32X2(acc[1][2], a01.y, w23.x, acc[1][2]);
        FMA_F32X2(acc[1][3], a01.y, w23.y, acc[1][3]);
        FMA_F32X2(acc[2][0], a23.x, w01.x, acc[2][0]);
        FMA_F32X2(acc[2][1], a23.x, w01.y, acc[2][1]);
        FMA_F32X2(acc[2][2], a23.x, w23.x, acc[2][2]);
        FMA_F32X2(acc[2][3], a23.x, w23.y, acc[2][3]);
        FMA_F32X2(acc[3][0], a23.y, w01.x, acc[3][0]);
        FMA_F32X2(acc[3][1], a23.y, w01.y, acc[3][1]);
        FMA_F32X2(acc[3][2], a23.y, w23.x, acc[3][2]);
        FMA_F32X2(acc[3][3], a23.y, w23.y, acc[3][3]);
    }

    float4 bb = *reinterpret_cast<const float4*>(&b[f4]);
#pragma unroll
    for (int p = 0; p < 4; p++) {
        unsigned lo0, hi0, lo1, hi1, lo2, hi2, lo3, hi3;
        UNPACK2(lo0, hi0, acc[p][0]);
        UNPACK2(lo1, hi1, acc[p][1]);
        UNPACK2(lo2, hi2, acc[p][2]);
        UNPACK2(lo3, hi3, acc[p][3]);
        int node_e = node0 + wg * 8 + 2 * p;
        if (node_e < n) {
            float4 xv = *reinterpret_cast<const float4*>(&x[(size_t)node_e * D + f4]);
            float4 o;
            o.x = xv.x + fmaxf(__uint_as_float(lo0) + bb.x, 0.f);
            o.y = xv.y + fmaxf(__uint_as_float(lo1) + bb.y, 0.f);
            o.z = xv.z + fmaxf(__uint_as_float(lo2) + bb.z, 0.f);
            o.w = xv.w + fmaxf(__uint_as_float(lo3) + bb.w, 0.f);
            *reinterpret_cast<float4*>(&out[(size_t)node_e * D + f4]) = o;
        }
        int node_o = node_e + 1;
        if (node_o < n) {
            float4 xv = *reinterpret_cast<const float4*>(&x[(size_t)node_o * D + f4]);
            float4 o;
            o.x = xv.x + fmaxf(__uint_as_float(hi0) + bb.x, 0.f);
            o.y = xv.y + fmaxf(__uint_as_float(hi1) + bb.y, 0.f);
            o.z = xv.z + fmaxf(__uint_as_float(hi2) + bb.z, 0.f);
            o.w = xv.w + fmaxf(__uint_as_float(hi3) + bb.w, 0.f);
            *reinterpret_cast<float4*>(&out[(size_t)node_o * D + f4]) = o;
        }
    }
}

// ---------------------------------------------------------------------------
extern "C" void kernel_launch(void* const* d_in, const int* in_sizes, int n_in,
                              void* d_out, int out_size) {
    const float* x = (const float*)d_in[0];
    const void* edge = d_in[1];
    const float* W = (const float*)d_in[2];
    const float* b = (const float*)d_in[3];
    float* out = (float*)d_out;

    int n = in_sizes[0] / D;  // 50000
    int E = in_sizes[1] / 2;  // 1,600,000
    if (E > EMAX) E = EMAX;

    void* cnt_ptr = nullptr;
    cudaGetSymbolAddress(&cnt_ptr, g_cntf);  // host-side query, no alloc
    cudaMemsetAsync(cnt_ptr, 0, (size_t)n * sizeof(float));

    fill_kernel<<<(E / 4 + 255) / 256, 256>>>(edge, E, in_sizes[1]);
    wtrans_kernel<<<64, 256>>>(W);
    prescale_kernel<<<(n * 32 + 255) / 256, 256>>>((const float4*)x, n);
    gather_kernel<<<(n + 7) / 8, 256>>>(n);
    gemm_relu_kernel<<<(n + 63) / 64, 256>>>(x, b, out, n);
}

// round 13
// speedup vs baseline: 1.3481x; 1.3481x over previous
#include <cuda_runtime.h>
#include <cuda_fp16.h>
#include <cstdint>

#define NMAX 50000
#define EMAX 1600000
#define D 128
#define CAP 128    // per-node bucket capacity; P(Poisson(32) > 128) ~ 1e-40

// Scratch (device globals: no runtime allocation allowed)
__device__ float    g_cntf[NMAX];                  // in-degree (float, exact)
__device__ int      g_bucket[(size_t)NMAX * CAP];  // src lists, node-strided
__device__ uint2    g_xsh[(size_t)NMAX * 32];      // x*dinv as half2 pairs
__device__ unsigned g_aggh[(size_t)NMAX * 64];     // agg as half2 (64 uint/row)
__device__ unsigned g_Wh[(size_t)D * 64];          // W fp16 [f][k] as half2

__device__ __forceinline__ unsigned h2_bits(__half2 h) {
    return *reinterpret_cast<unsigned*>(&h);
}
__device__ __forceinline__ float2 bits_f2(unsigned u) {
    __half2 h = *reinterpret_cast<__half2*>(&u);
    return __half22float2(h);
}

// ---------------------------------------------------------------------------
// fill: bucket edges by dst, 4 edges per thread (overlapped atomic chains).
// Per-block inline dtype detection (int64 values < 2^31 -> odd words zero).
// ---------------------------------------------------------------------------
__global__ void fill_kernel(const void* __restrict__ edge, int E, int nwords) {
    int flag = 0;
    const int* e32 = (const int*)edge;
    for (int i = 1 + 2 * threadIdx.x; i < 2048 && i < nwords;
         i += 2 * blockDim.x)
        flag |= e32[i];
    int is64 = !__syncthreads_or(flag);

    int base = (blockIdx.x * blockDim.x + threadIdx.x) * 4;
    int s[4], d[4], pos[4];
#pragma unroll
    for (int j = 0; j < 4; j++) {
        int i = base + j;
        if (i < E) {
            if (is64) {
                const long long* e64 = (const long long*)edge;
                s[j] = (int)e64[i];
                d[j] = (int)e64[E + i];
            } else {
                s[j] = e32[i];
                d[j] = e32[E + i];
            }
        } else {
            s[j] = 0;
            d[j] = -1;
        }
    }
#pragma unroll
    for (int j = 0; j < 4; j++)
        if (d[j] >= 0) pos[j] = (int)atomicAdd(&g_cntf[d[j]], 1.0f);
#pragma unroll
    for (int j = 0; j < 4; j++)
        if (d[j] >= 0 && pos[j] < CAP)
            g_bucket[(size_t)d[j] * CAP + pos[j]] = s[j];
}

// ---------------------------------------------------------------------------
// wtrans: g_Wh[f][k] = fp16(W[f][k])  (half2-packed, k contiguous)
// ---------------------------------------------------------------------------
__global__ void wtrans_kernel(const float* __restrict__ W) {
    int j = blockIdx.x * blockDim.x + threadIdx.x;  // uint index: f*64 + k/2
    if (j >= D * 64) return;
    int f = j >> 6;
    int k2 = (j & 63) * 2;
    g_Wh[j] = h2_bits(__floats2half2_rn(W[f * D + k2], W[f * D + k2 + 1]));
}

// ---------------------------------------------------------------------------
// prescale: xsh[i] = half(x[i] * dinv(i))   (dinv = rsqrt(deg+1))
// ---------------------------------------------------------------------------
__global__ void prescale_kernel(const float4* __restrict__ x4, int n) {
    int i = blockIdx.x * blockDim.x + threadIdx.x;
    if (i >= n * 32) return;
    int node = i >> 5;
    float dd = rsqrtf(g_cntf[node] + 1.0f);
    float4 v = __ldg(&x4[i]);
    uint2 u;
    u.x = h2_bits(__floats2half2_rn(v.x * dd, v.y * dd));
    u.y = h2_bits(__floats2half2_rn(v.z * dd, v.w * dd));
    g_xsh[i] = u;
}

// ---------------------------------------------------------------------------
// gather-aggregate. One warp per dst node, lane = 4-feature chunk, unroll-8.
// fp32 accumulation; output row scaled by dinv[dst], stored as fp16 (half2x2)
// ---------------------------------------------------------------------------
__global__ __launch_bounds__(256) void gather_kernel(int n) {
    int node = blockIdx.x * 8 + (threadIdx.x >> 5);
    int lane = threadIdx.x & 31;
    if (node >= n) return;
    const int* row = &g_bucket[(size_t)node * CAP];
    int deg = (int)g_cntf[node];
    if (deg > CAP) deg = CAP;
    float dd = rsqrtf((float)deg + 1.0f);

    float4 a[8];
#pragma unroll
    for (int j = 0; j < 8; j++) a[j] = make_float4(0.f, 0.f, 0.f, 0.f);

    // self-loop contribution
    {
        uint2 u = g_xsh[(size_t)node * 32 + lane];
        float2 lo = bits_f2(u.x);
        float2 hi = bits_f2(u.y);
        a[0] = make_float4(lo.x, lo.y, hi.x, hi.y);
    }

    int e = 0;
    for (; e + 8 <= deg; e += 8) {
        int s[8];
        uint2 u[8];
#pragma unroll
        for (int j = 0; j < 8; j++) s[j] = row[e + j];
#pragma unroll
        for (int j = 0; j < 8; j++) u[j] = __ldg(&g_xsh[(size_t)s[j] * 32 + lane]);
#pragma unroll
        for (int j = 0; j < 8; j++) {
            float2 lo = bits_f2(u[j].x);
            float2 hi = bits_f2(u[j].y);
            a[j].x += lo.x;
            a[j].y += lo.y;
            a[j].z += hi.x;
            a[j].w += hi.y;
        }
    }
    for (; e < deg; e++) {
        int s = row[e];
        uint2 u = __ldg(&g_xsh[(size_t)s * 32 + lane]);
        float2 lo = bits_f2(u.x);
        float2 hi = bits_f2(u.y);
        a[0].x += lo.x; a[0].y += lo.y; a[0].z += hi.x; a[0].w += hi.y;
    }
    float4 acc;
    acc.x = ((a[0].x + a[1].x) + (a[2].x + a[3].x)) + ((a[4].x + a[5].x) + (a[6].x + a[7].x));
    acc.y = ((a[0].y + a[1].y) + (a[2].y + a[3].y)) + ((a[4].y + a[5].y) + (a[6].y + a[7].y));
    acc.z = ((a[0].z + a[1].z) + (a[2].z + a[3].z)) + ((a[4].z + a[5].z) + (a[6].z + a[7].z));
    acc.w = ((a[0].w + a[1].w) + (a[2].w + a[3].w)) + ((a[4].w + a[5].w) + (a[6].w + a[7].w));
    uint2 o;
    o.x = h2_bits(__floats2half2_rn(acc.x * dd, acc.y * dd));
    o.y = h2_bits(__floats2half2_rn(acc.z * dd, acc.w * dd));
    reinterpret_cast<uint2*>(g_aggh)[(size_t)node * 32 + lane] = o;
}

// ---------------------------------------------------------------------------
// GEMM via mma.sync.m16n8k16 (f16 in, f32 accum), no smem.
// Block = 256 threads = 8 warps; warp wm owns 16 nodes (m-tile), covers all
// 128 features (16 n-tiles), k in 8 k-tiles.
// A = g_aggh [node][k] row-major fp16; B = g_Wh [f][k] = col-major [n][k]. ✓
// Epilogue: out = x + relu(h + bias), float2 stores.
// ---------------------------------------------------------------------------
__global__ __launch_bounds__(256) void gemm_mma_kernel(
    const float* __restrict__ x, const float* __restrict__ b,
    float* __restrict__ out, int n) {
    int lane = threadIdx.x & 31;
    int wm = threadIdx.x >> 5;       // warp's m-tile
    int g = lane >> 2;               // group id 0..7
    int tig = lane & 3;              // thread in group

    int r0 = blockIdx.x * 128 + wm * 16 + g;  // A rows this thread touches
    int r1 = r0 + 8;

    float dacc[16][4];
#pragma unroll
    for (int nt = 0; nt < 16; nt++)
#pragma unroll
        for (int c = 0; c < 4; c++) dacc[nt][c] = 0.f;

#pragma unroll
    for (int kt = 0; kt < 8; kt++) {
        int ku = kt * 8 + tig;  // uint index of half2 (k = 2*ku)
        unsigned a0 = 0, a1 = 0, a2 = 0, a3 = 0;
        if (r0 < n) {
            a0 = __ldg(&g_aggh[(size_t)r0 * 64 + ku]);
            a2 = __ldg(&g_aggh[(size_t)r0 * 64 + ku + 4]);
        }
        if (r1 < n) {
            a1 = __ldg(&g_aggh[(size_t)r1 * 64 + ku]);
            a3 = __ldg(&g_aggh[(size_t)r1 * 64 + ku + 4]);
        }
#pragma unroll
        for (int nt = 0; nt < 16; nt++) {
            int f = nt * 8 + g;  // B column (n) for this thread
            unsigned b0 = __ldg(&g_Wh[(size_t)f * 64 + ku]);
            unsigned b1 = __ldg(&g_Wh[(size_t)f * 64 + ku + 4]);
            asm volatile(
                "mma.sync.aligned.m16n8k16.row.col.f32.f16.f16.f32 "
                "{%0,%1,%2,%3}, {%4,%5,%6,%7}, {%8,%9}, {%0,%1,%2,%3};"
                : "+f"(dacc[nt][0]), "+f"(dacc[nt][1]), "+f"(dacc[nt][2]),
                  "+f"(dacc[nt][3])
                : "r"(a0), "r"(a1), "r"(a2), "r"(a3), "r"(b0), "r"(b1));
        }
    }

    // Epilogue. C frag: c0,c1 = row g,   cols 2tig, 2tig+1 (within n-tile)
    //                   c2,c3 = row g+8, cols 2tig, 2tig+1
#pragma unroll
    for (int nt = 0; nt < 16; nt++) {
        int f0 = nt * 8 + 2 * tig;
        float2 bb = *reinterpret_cast<const float2*>(&b[f0]);
        if (r0 < n) {
            float2 xv = *reinterpret_cast<const float2*>(&x[(size_t)r0 * D + f0]);
            float2 o;
            o.x = xv.x + fmaxf(dacc[nt][0] + bb.x, 0.f);
            o.y = xv.y + fmaxf(dacc[nt][1] + bb.y, 0.f);
            *reinterpret_cast<float2*>(&out[(size_t)r0 * D + f0]) = o;
        }
        if (r1 < n) {
            float2 xv = *reinterpret_cast<const float2*>(&x[(size_t)r1 * D + f0]);
            float2 o;
            o.x = xv.x + fmaxf(dacc[nt][2] + bb.x, 0.f);
            o.y = xv.y + fmaxf(dacc[nt][3] + bb.y, 0.f);
            *reinterpret_cast<float2*>(&out[(size_t)r1 * D + f0]) = o;
        }
    }
}

// ---------------------------------------------------------------------------
extern "C" void kernel_launch(void* const* d_in, const int* in_sizes, int n_in,
                              void* d_out, int out_size) {
    const float* x = (const float*)d_in[0];
    const void* edge = d_in[1];
    const float* W = (const float*)d_in[2];
    const float* b = (const float*)d_in[3];
    float* out = (float*)d_out;

    int n = in_sizes[0] / D;  // 50000
    int E = in_sizes[1] / 2;  // 1,600,000
    if (E > EMAX) E = EMAX;

    void* cnt_ptr = nullptr;
    cudaGetSymbolAddress(&cnt_ptr, g_cntf);  // host-side query, no alloc
    cudaMemsetAsync(cnt_ptr, 0, (size_t)n * sizeof(float));

    fill_kernel<<<(E / 4 + 255) / 256, 256>>>(edge, E, in_sizes[1]);
    wtrans_kernel<<<32, 256>>>(W);
    prescale_kernel<<<(n * 32 + 255) / 256, 256>>>((const float4*)x, n);
    gather_kernel<<<(n + 7) / 8, 256>>>(n);
    gemm_mma_kernel<<<(n + 127) / 128, 256>>>(x, b, out, n);
}

// round 14
// speedup vs baseline: 1.5622x; 1.1588x over previous
#include <cuda_runtime.h>
#include <cuda_fp16.h>
#include <cstdint>

#define NMAX 50000
#define EMAX 1600000
#define D 128
#define CAP 128    // per-node bucket capacity; P(Poisson(32) > 128) ~ 1e-40

// Scratch (device globals: no runtime allocation allowed)
__device__ float    g_cntf[NMAX];                  // in-degree (float, exact)
__device__ int      g_bucket[(size_t)NMAX * CAP];  // src lists, node-strided
__device__ uint2    g_xsh[(size_t)NMAX * 32];      // x*dinv as half2 pairs
__device__ unsigned g_aggh[(size_t)NMAX * 64];     // agg as half2 (64 uint/row)
__device__ unsigned g_Wh[(size_t)D * 64];          // W fp16 [f][k] as half2

__device__ __forceinline__ unsigned h2_bits(__half2 h) {
    return *reinterpret_cast<unsigned*>(&h);
}
__device__ __forceinline__ __half2 bits_h2(unsigned u) {
    return *reinterpret_cast<__half2*>(&u);
}
__device__ __forceinline__ float2 bits_f2(unsigned u) {
    __half2 h = *reinterpret_cast<__half2*>(&u);
    return __half22float2(h);
}

// ---------------------------------------------------------------------------
// fill: bucket edges by dst, 4 edges per thread (overlapped atomic chains).
// Per-block inline dtype detection (int64 values < 2^31 -> odd words zero).
// ---------------------------------------------------------------------------
__global__ void fill_kernel(const void* __restrict__ edge, int E, int nwords) {
    int flag = 0;
    const int* e32 = (const int*)edge;
    for (int i = 1 + 2 * threadIdx.x; i < 2048 && i < nwords;
         i += 2 * blockDim.x)
        flag |= e32[i];
    int is64 = !__syncthreads_or(flag);

    int base = (blockIdx.x * blockDim.x + threadIdx.x) * 4;
    int s[4], d[4], pos[4];
#pragma unroll
    for (int j = 0; j < 4; j++) {
        int i = base + j;
        if (i < E) {
            if (is64) {
                const long long* e64 = (const long long*)edge;
                s[j] = (int)e64[i];
                d[j] = (int)e64[E + i];
            } else {
                s[j] = e32[i];
                d[j] = e32[E + i];
            }
        } else {
            s[j] = 0;
            d[j] = -1;
        }
    }
#pragma unroll
    for (int j = 0; j < 4; j++)
        if (d[j] >= 0) pos[j] = (int)atomicAdd(&g_cntf[d[j]], 1.0f);
#pragma unroll
    for (int j = 0; j < 4; j++)
        if (d[j] >= 0 && pos[j] < CAP)
            g_bucket[(size_t)d[j] * CAP + pos[j]] = s[j];
}

// ---------------------------------------------------------------------------
// prescale (+W convert folded in): xsh[i] = half(x[i] * dinv(i));
// first D*64 threads also convert W to fp16 half2 ([f][k], k contiguous).
// ---------------------------------------------------------------------------
__global__ void prescale_kernel(const float4* __restrict__ x4,
                                const float* __restrict__ W, int n) {
    int i = blockIdx.x * blockDim.x + threadIdx.x;
    if (i < D * 64) {
        int f = i >> 6;
        int k2 = (i & 63) * 2;
        g_Wh[i] = h2_bits(__floats2half2_rn(W[f * D + k2], W[f * D + k2 + 1]));
    }
    if (i >= n * 32) return;
    int node = i >> 5;
    float dd = rsqrtf(g_cntf[node] + 1.0f);
    float4 v = __ldg(&x4[i]);
    uint2 u;
    u.x = h2_bits(__floats2half2_rn(v.x * dd, v.y * dd));
    u.y = h2_bits(__floats2half2_rn(v.z * dd, v.w * dd));
    g_xsh[i] = u;
}

// ---------------------------------------------------------------------------
// gather-aggregate. One warp per dst node, lane = 4-feature chunk, unroll-8.
// Per 8-edge batch: fp16 HADD2 depth-3 tree (14 ops), one fp32 flush
// (4 cvt + 4 FADD). fp32 running accumulator; output stored as fp16.
// ---------------------------------------------------------------------------
__global__ __launch_bounds__(256) void gather_kernel(int n) {
    int node = blockIdx.x * 8 + (threadIdx.x >> 5);
    int lane = threadIdx.x & 31;
    if (node >= n) return;
    const int* row = &g_bucket[(size_t)node * CAP];
    int deg = (int)g_cntf[node];
    if (deg > CAP) deg = CAP;
    float dd = rsqrtf((float)deg + 1.0f);

    float4 acc;
    // self-loop contribution (fp32)
    {
        uint2 u = g_xsh[(size_t)node * 32 + lane];
        float2 lo = bits_f2(u.x);
        float2 hi = bits_f2(u.y);
        acc = make_float4(lo.x, lo.y, hi.x, hi.y);
    }

    int e = 0;
    for (; e + 8 <= deg; e += 8) {
        int s[8];
        uint2 u[8];
#pragma unroll
        for (int j = 0; j < 8; j++) s[j] = row[e + j];
#pragma unroll
        for (int j = 0; j < 8; j++) u[j] = __ldg(&g_xsh[(size_t)s[j] * 32 + lane]);
        // fp16 pairwise tree, component x (features 0,1)
        __half2 x01 = __hadd2(bits_h2(u[0].x), bits_h2(u[1].x));
        __half2 x23 = __hadd2(bits_h2(u[2].x), bits_h2(u[3].x));
        __half2 x45 = __hadd2(bits_h2(u[4].x), bits_h2(u[5].x));
        __half2 x67 = __hadd2(bits_h2(u[6].x), bits_h2(u[7].x));
        __half2 xa = __hadd2(x01, x23);
        __half2 xb = __hadd2(x45, x67);
        __half2 xt = __hadd2(xa, xb);
        // component y (features 2,3)
        __half2 y01 = __hadd2(bits_h2(u[0].y), bits_h2(u[1].y));
        __half2 y23 = __hadd2(bits_h2(u[2].y), bits_h2(u[3].y));
        __half2 y45 = __hadd2(bits_h2(u[4].y), bits_h2(u[5].y));
        __half2 y67 = __hadd2(bits_h2(u[6].y), bits_h2(u[7].y));
        __half2 ya = __hadd2(y01, y23);
        __half2 yb = __hadd2(y45, y67);
        __half2 yt = __hadd2(ya, yb);
        // flush to fp32
        float2 fx = __half22float2(xt);
        float2 fy = __half22float2(yt);
        acc.x += fx.x;
        acc.y += fx.y;
        acc.z += fy.x;
        acc.w += fy.y;
    }
    for (; e < deg; e++) {
        int s = row[e];
        uint2 u = __ldg(&g_xsh[(size_t)s * 32 + lane]);
        float2 lo = bits_f2(u.x);
        float2 hi = bits_f2(u.y);
        acc.x += lo.x; acc.y += lo.y; acc.z += hi.x; acc.w += hi.y;
    }
    uint2 o;
    o.x = h2_bits(__floats2half2_rn(acc.x * dd, acc.y * dd));
    o.y = h2_bits(__floats2half2_rn(acc.z * dd, acc.w * dd));
    reinterpret_cast<uint2*>(g_aggh)[(size_t)node * 32 + lane] = o;
}

// ---------------------------------------------------------------------------
// GEMM via mma.sync.m16n8k16 (f16 in, f32 accum), no smem.
// Block = 256 threads = 8 warps; warp wm owns 16 nodes (m-tile), covers all
// 128 features (16 n-tiles), k in 8 k-tiles.
// A = g_aggh [node][k] row-major fp16; B = g_Wh [f][k] = col-major [n][k].
// Epilogue: out = x + relu(h + bias), float2 stores.
// ---------------------------------------------------------------------------
__global__ __launch_bounds__(256) void gemm_mma_kernel(
    const float* __restrict__ x, const float* __restrict__ b,
    float* __restrict__ out, int n) {
    int lane = threadIdx.x & 31;
    int wm = threadIdx.x >> 5;       // warp's m-tile
    int g = lane >> 2;               // group id 0..7
    int tig = lane & 3;              // thread in group

    int r0 = blockIdx.x * 128 + wm * 16 + g;  // A rows this thread touches
    int r1 = r0 + 8;

    float dacc[16][4];
#pragma unroll
    for (int nt = 0; nt < 16; nt++)
#pragma unroll
        for (int c = 0; c < 4; c++) dacc[nt][c] = 0.f;

#pragma unroll
    for (int kt = 0; kt < 8; kt++) {
        int ku = kt * 8 + tig;  // uint index of half2 (k = 2*ku)
        unsigned a0 = 0, a1 = 0, a2 = 0, a3 = 0;
        if (r0 < n) {
            a0 = __ldg(&g_aggh[(size_t)r0 * 64 + ku]);
            a2 = __ldg(&g_aggh[(size_t)r0 * 64 + ku + 4]);
        }
        if (r1 < n) {
            a1 = __ldg(&g_aggh[(size_t)r1 * 64 + ku]);
            a3 = __ldg(&g_aggh[(size_t)r1 * 64 + ku + 4]);
        }
#pragma unroll
        for (int nt = 0; nt < 16; nt++) {
            int f = nt * 8 + g;  // B column (n) for this thread
            unsigned b0 = __ldg(&g_Wh[(size_t)f * 64 + ku]);
            unsigned b1 = __ldg(&g_Wh[(size_t)f * 64 + ku + 4]);
            asm volatile(
                "mma.sync.aligned.m16n8k16.row.col.f32.f16.f16.f32 "
                "{%0,%1,%2,%3}, {%4,%5,%6,%7}, {%8,%9}, {%0,%1,%2,%3};"
                : "+f"(dacc[nt][0]), "+f"(dacc[nt][1]), "+f"(dacc[nt][2]),
                  "+f"(dacc[nt][3])
                : "r"(a0), "r"(a1), "r"(a2), "r"(a3), "r"(b0), "r"(b1));
        }
    }

    // Epilogue. C frag: c0,c1 = row g,   cols 2tig, 2tig+1 (within n-tile)
    //                   c2,c3 = row g+8, cols 2tig, 2tig+1
#pragma unroll
    for (int nt = 0; nt < 16; nt++) {
        int f0 = nt * 8 + 2 * tig;
        float2 bb = *reinterpret_cast<const float2*>(&b[f0]);
        if (r0 < n) {
            float2 xv = *reinterpret_cast<const float2*>(&x[(size_t)r0 * D + f0]);
            float2 o;
            o.x = xv.x + fmaxf(dacc[nt][0] + bb.x, 0.f);
            o.y = xv.y + fmaxf(dacc[nt][1] + bb.y, 0.f);
            *reinterpret_cast<float2*>(&out[(size_t)r0 * D + f0]) = o;
        }
        if (r1 < n) {
            float2 xv = *reinterpret_cast<const float2*>(&x[(size_t)r1 * D + f0]);
            float2 o;
            o.x = xv.x + fmaxf(dacc[nt][2] + bb.x, 0.f);
            o.y = xv.y + fmaxf(dacc[nt][3] + bb.y, 0.f);
            *reinterpret_cast<float2*>(&out[(size_t)r1 * D + f0]) = o;
        }
    }
}

// ---------------------------------------------------------------------------
extern "C" void kernel_launch(void* const* d_in, const int* in_sizes, int n_in,
                              void* d_out, int out_size) {
    const float* x = (const float*)d_in[0];
    const void* edge = d_in[1];
    const float* W = (const float*)d_in[2];
    const float* b = (const float*)d_in[3];
    float* out = (float*)d_out;

    int n = in_sizes[0] / D;  // 50000
    int E = in_sizes[1] / 2;  // 1,600,000
    if (E > EMAX) E = EMAX;

    void* cnt_ptr = nullptr;
    cudaGetSymbolAddress(&cnt_ptr, g_cntf);  // host-side query, no alloc
    cudaMemsetAsync(cnt_ptr, 0, (size_t)n * sizeof(float));

    fill_kernel<<<(E / 4 + 255) / 256, 256>>>(edge, E, in_sizes[1]);
    prescale_kernel<<<(n * 32 + 255) / 256, 256>>>((const float4*)x, W, n);
    gather_kernel<<<(n + 7) / 8, 256>>>(n);
    gemm_mma_kernel<<<(n + 127) / 128, 256>>>(x, b, out, n);
}

// round 15
// speedup vs baseline: 1.8964x; 1.2139x over previous
#include <cuda_runtime.h>
#include <cuda_fp16.h>
#include <cstdint>

#define NMAX 50000
#define EMAX 1600000
#define D 128
#define CAP 128     // per-node bucket capacity; P(Poisson(32) > 128) ~ 1e-40
#define WSTRIDE 68  // Wsm row stride in uints: 4f mod 32 distinct -> ldmatrix conflict-free

// Scratch (device globals: no runtime allocation allowed)
__device__ float    g_cntf[NMAX];                  // in-degree (float, exact)
__device__ int      g_bucket[(size_t)NMAX * CAP];  // src lists, node-strided
__device__ uint2    g_xsh[(size_t)NMAX * 32];      // x*dinv as half2 pairs
__device__ unsigned g_aggh[(size_t)NMAX * 64];     // agg as half2 (64 uint/row)
__device__ unsigned g_Wh[(size_t)D * 64];          // W fp16 [f][k] as half2

__device__ __forceinline__ unsigned h2_bits(__half2 h) {
    return *reinterpret_cast<unsigned*>(&h);
}
__device__ __forceinline__ __half2 bits_h2(unsigned u) {
    return *reinterpret_cast<__half2*>(&u);
}
__device__ __forceinline__ float2 bits_f2(unsigned u) {
    __half2 h = *reinterpret_cast<__half2*>(&u);
    return __half22float2(h);
}

// ---------------------------------------------------------------------------
// fill: bucket edges by dst, 4 edges per thread (overlapped atomic chains).
// Per-block inline dtype detection (int64 values < 2^31 -> odd words zero).
// ---------------------------------------------------------------------------
__global__ void fill_kernel(const void* __restrict__ edge, int E, int nwords) {
    int flag = 0;
    const int* e32 = (const int*)edge;
    for (int i = 1 + 2 * threadIdx.x; i < 2048 && i < nwords;
         i += 2 * blockDim.x)
        flag |= e32[i];
    int is64 = !__syncthreads_or(flag);

    int base = (blockIdx.x * blockDim.x + threadIdx.x) * 4;
    int s[4], d[4], pos[4];
#pragma unroll
    for (int j = 0; j < 4; j++) {
        int i = base + j;
        if (i < E) {
            if (is64) {
                const long long* e64 = (const long long*)edge;
                s[j] = (int)e64[i];
                d[j] = (int)e64[E + i];
            } else {
                s[j] = e32[i];
                d[j] = e32[E + i];
            }
        } else {
            s[j] = 0;
            d[j] = -1;
        }
    }
#pragma unroll
    for (int j = 0; j < 4; j++)
        if (d[j] >= 0) pos[j] = (int)atomicAdd(&g_cntf[d[j]], 1.0f);
#pragma unroll
    for (int j = 0; j < 4; j++)
        if (d[j] >= 0 && pos[j] < CAP)
            g_bucket[(size_t)d[j] * CAP + pos[j]] = s[j];
}

// ---------------------------------------------------------------------------
// prescale (+W convert folded in): xsh[i] = half(x[i] * dinv(i));
// first D*64 threads also convert W to fp16 half2 ([f][k], k contiguous).
// ---------------------------------------------------------------------------
__global__ void prescale_kernel(const float4* __restrict__ x4,
                                const float* __restrict__ W, int n) {
    int i = blockIdx.x * blockDim.x + threadIdx.x;
    if (i < D * 64) {
        int f = i >> 6;
        int k2 = (i & 63) * 2;
        g_Wh[i] = h2_bits(__floats2half2_rn(W[f * D + k2], W[f * D + k2 + 1]));
    }
    if (i >= n * 32) return;
    int node = i >> 5;
    float dd = rsqrtf(g_cntf[node] + 1.0f);
    float4 v = __ldg(&x4[i]);
    uint2 u;
    u.x = h2_bits(__floats2half2_rn(v.x * dd, v.y * dd));
    u.y = h2_bits(__floats2half2_rn(v.z * dd, v.w * dd));
    g_xsh[i] = u;
}

// ---------------------------------------------------------------------------
// gather-aggregate. One warp per dst node, lane = 4-feature chunk, unroll-8.
// fp16 HADD2 depth-3 tree per batch, fp32 running accumulator, fp16 output.
// ---------------------------------------------------------------------------
__global__ __launch_bounds__(256) void gather_kernel(int n) {
    int node = blockIdx.x * 8 + (threadIdx.x >> 5);
    int lane = threadIdx.x & 31;
    if (node >= n) return;
    const int* row = &g_bucket[(size_t)node * CAP];
    int deg = (int)g_cntf[node];
    if (deg > CAP) deg = CAP;
    float dd = rsqrtf((float)deg + 1.0f);

    float4 acc;
    {
        uint2 u = g_xsh[(size_t)node * 32 + lane];
        float2 lo = bits_f2(u.x);
        float2 hi = bits_f2(u.y);
        acc = make_float4(lo.x, lo.y, hi.x, hi.y);
    }

    int e = 0;
    for (; e + 8 <= deg; e += 8) {
        int s[8];
        uint2 u[8];
#pragma unroll
        for (int j = 0; j < 8; j++) s[j] = row[e + j];
#pragma unroll
        for (int j = 0; j < 8; j++) u[j] = __ldg(&g_xsh[(size_t)s[j] * 32 + lane]);
        __half2 x01 = __hadd2(bits_h2(u[0].x), bits_h2(u[1].x));
        __half2 x23 = __hadd2(bits_h2(u[2].x), bits_h2(u[3].x));
        __half2 x45 = __hadd2(bits_h2(u[4].x), bits_h2(u[5].x));
        __half2 x67 = __hadd2(bits_h2(u[6].x), bits_h2(u[7].x));
        __half2 xt = __hadd2(__hadd2(x01, x23), __hadd2(x45, x67));
        __half2 y01 = __hadd2(bits_h2(u[0].y), bits_h2(u[1].y));
        __half2 y23 = __hadd2(bits_h2(u[2].y), bits_h2(u[3].y));
        __half2 y45 = __hadd2(bits_h2(u[4].y), bits_h2(u[5].y));
        __half2 y67 = __hadd2(bits_h2(u[6].y), bits_h2(u[7].y));
        __half2 yt = __hadd2(__hadd2(y01, y23), __hadd2(y45, y67));
        float2 fx = __half22float2(xt);
        float2 fy = __half22float2(yt);
        acc.x += fx.x;
        acc.y += fx.y;
        acc.z += fy.x;
        acc.w += fy.y;
    }
    for (; e < deg; e++) {
        int s = row[e];
        uint2 u = __ldg(&g_xsh[(size_t)s * 32 + lane]);
        float2 lo = bits_f2(u.x);
        float2 hi = bits_f2(u.y);
        acc.x += lo.x; acc.y += lo.y; acc.z += hi.x; acc.w += hi.y;
    }
    uint2 o;
    o.x = h2_bits(__floats2half2_rn(acc.x * dd, acc.y * dd));
    o.y = h2_bits(__floats2half2_rn(acc.z * dd, acc.w * dd));
    reinterpret_cast<uint2*>(g_aggh)[(size_t)node * 32 + lane] = o;
}

// ---------------------------------------------------------------------------
// GEMM via mma.sync.m16n8k16 (f16 in, f32 accum).
// W staged in padded smem once per block; B fragments via ldmatrix.x4
// (2 n-tiles per instr, conflict-free with WSTRIDE=68). A frags direct LDG.
// Block = 256 threads = 8 warps; warp wm owns 16 nodes, all 128 features.
// ---------------------------------------------------------------------------
__global__ __launch_bounds__(256) void gemm_mma_kernel(
    const float* __restrict__ x, const float* __restrict__ b,
    float* __restrict__ out, int n) {
    __shared__ unsigned Wsm[D * WSTRIDE];  // [f][ku], padded rows

    int tid = threadIdx.x;
    // stage W (coalesced LDG, strided STS)
    for (int i = tid; i < D * 64; i += 256) {
        int f = i >> 6;
        int ku = i & 63;
        Wsm[f * WSTRIDE + ku] = g_Wh[i];
    }
    __syncthreads();

    int lane = tid & 31;
    int wm = tid >> 5;
    int g = lane >> 2;
    int tig = lane & 3;

    int r0 = blockIdx.x * 128 + wm * 16 + g;
    int r1 = r0 + 8;

    // per-lane ldmatrix base for B: grp 0,1 -> nt even rows, halves 0,1;
    // grp 2,3 -> nt odd rows, halves 0,1.
    int grp = lane >> 3;
    int lr = lane & 7;
    int fb = ((grp >> 1) << 3) + lr;   // 0..15 within the ntp's 16 f-rows
    int hof = (grp & 1) * 4;           // uint offset for the k+8 half
    unsigned wbase = (unsigned)__cvta_generic_to_shared(Wsm);

    float dacc[16][4];
#pragma unroll
    for (int nt = 0; nt < 16; nt++)
#pragma unroll
        for (int c = 0; c < 4; c++) dacc[nt][c] = 0.f;

#pragma unroll
    for (int kt = 0; kt < 8; kt++) {
        int ku = kt * 8 + tig;
        unsigned a0 = 0, a1 = 0, a2 = 0, a3 = 0;
        if (r0 < n) {
            a0 = __ldg(&g_aggh[(size_t)r0 * 64 + ku]);
            a2 = __ldg(&g_aggh[(size_t)r0 * 64 + ku + 4]);
        }
        if (r1 < n) {
            a1 = __ldg(&g_aggh[(size_t)r1 * 64 + ku]);
            a3 = __ldg(&g_aggh[(size_t)r1 * 64 + ku + 4]);
        }
#pragma unroll
        for (int ntp = 0; ntp < 8; ntp++) {
            // lane's row pointer: f = ntp*16 + fb, uint col = kt*8 + hof
            unsigned addr =
                wbase + (((ntp * 16 + fb) * WSTRIDE + kt * 8 + hof) << 2);
            unsigned b0, b1, b2, b3;
            asm volatile(
                "ldmatrix.sync.aligned.m8n8.x4.shared.b16 {%0,%1,%2,%3}, [%4];"
                : "=r"(b0), "=r"(b1), "=r"(b2), "=r"(b3)
                : "r"(addr));
            asm volatile(
                "mma.sync.aligned.m16n8k16.row.col.f32.f16.f16.f32 "
                "{%0,%1,%2,%3}, {%4,%5,%6,%7}, {%8,%9}, {%0,%1,%2,%3};"
                : "+f"(dacc[2 * ntp][0]), "+f"(dacc[2 * ntp][1]),
                  "+f"(dacc[2 * ntp][2]), "+f"(dacc[2 * ntp][3])
                : "r"(a0), "r"(a1), "r"(a2), "r"(a3), "r"(b0), "r"(b1));
            asm volatile(
                "mma.sync.aligned.m16n8k16.row.col.f32.f16.f16.f32 "
                "{%0,%1,%2,%3}, {%4,%5,%6,%7}, {%8,%9}, {%0,%1,%2,%3};"
                : "+f"(dacc[2 * ntp + 1][0]), "+f"(dacc[2 * ntp + 1][1]),
                  "+f"(dacc[2 * ntp + 1][2]), "+f"(dacc[2 * ntp + 1][3])
                : "r"(a0), "r"(a1), "r"(a2), "r"(a3), "r"(b2), "r"(b3));
        }
    }

    // Epilogue. C frag: c0,c1 = row g, cols 2tig,2tig+1; c2,c3 = row g+8.
#pragma unroll
    for (int nt = 0; nt < 16; nt++) {
        int f0 = nt * 8 + 2 * tig;
        float2 bb = *reinterpret_cast<const float2*>(&b[f0]);
        if (r0 < n) {
            float2 xv = *reinterpret_cast<const float2*>(&x[(size_t)r0 * D + f0]);
            float2 o;
            o.x = xv.x + fmaxf(dacc[nt][0] + bb.x, 0.f);
            o.y = xv.y + fmaxf(dacc[nt][1] + bb.y, 0.f);
            *reinterpret_cast<float2*>(&out[(size_t)r0 * D + f0]) = o;
        }
        if (r1 < n) {
            float2 xv = *reinterpret_cast<const float2*>(&x[(size_t)r1 * D + f0]);
            float2 o;
            o.x = xv.x + fmaxf(dacc[nt][2] + bb.x, 0.f);
            o.y = xv.y + fmaxf(dacc[nt][3] + bb.y, 0.f);
            *reinterpret_cast<float2*>(&out[(size_t)r1 * D + f0]) = o;
        }
    }
}

// ---------------------------------------------------------------------------
extern "C" void kernel_launch(void* const* d_in, const int* in_sizes, int n_in,
                              void* d_out, int out_size) {
    const float* x = (const float*)d_in[0];
    const void* edge = d_in[1];
    const float* W = (const float*)d_in[2];
    const float* b = (const float*)d_in[3];
    float* out = (float*)d_out;

    int n = in_sizes[0] / D;  // 50000
    int E = in_sizes[1] / 2;  // 1,600,000
    if (E > EMAX) E = EMAX;

    void* cnt_ptr = nullptr;
    cudaGetSymbolAddress(&cnt_ptr, g_cntf);  // host-side query, no alloc
    cudaMemsetAsync(cnt_ptr, 0, (size_t)n * sizeof(float));

    fill_kernel<<<(E / 4 + 255) / 256, 256>>>(edge, E, in_sizes[1]);
    prescale_kernel<<<(n * 32 + 255) / 256, 256>>>((const float4*)x, W, n);
    gather_kernel<<<(n + 7) / 8, 256>>>(n);
    gemm_mma_kernel<<<(n + 127) / 128, 256>>>(x, b, out, n);
}